// round 4
// baseline (speedup 1.0000x reference)
#include <cuda_runtime.h>
#include <cuda_fp16.h>
#include <math.h>
#include <stdint.h>

// Problem constants
#define BATCH 4
#define NTOK  2048
#define FEATS 1024
#define NHEAD 16
#define HDIM  64
#define MROWS (BATCH * NTOK)   // 8192
#define WSZ   (1024 * 1024)

// ---------------- scratch (device globals) ----------------
__device__ float g_q[MROWS * FEATS];
__device__ float g_k[MROWS * FEATS];
__device__ float g_v[MROWS * FEATS];
__device__ float g_S[64 * HDIM * HDIM];
__device__ float g_Sp[512 * HDIM * HDIM];
__device__ __half g_xh[MROWS * FEATS];
__device__ __half g_xl[MROWS * FEATS];
__device__ __half g_ah[MROWS * FEATS];
__device__ __half g_al[MROWS * FEATS];
__device__ __half g_wth[4 * WSZ];   // W^T hi  [N,K] per matrix
__device__ __half g_wtl[4 * WSZ];   // W^T lo

// ==================== PTX helpers ====================
#define CP_ASYNC16(dst, src) \
    asm volatile("cp.async.cg.shared.global [%0], [%1], 16;\n" :: "r"(dst), "l"(src))
#define CP_COMMIT() asm volatile("cp.async.commit_group;\n")
#define CP_WAIT2()  asm volatile("cp.async.wait_group 2;\n" ::: "memory")

#define LDMATRIX_X4(r0,r1,r2,r3,addr) \
    asm volatile("ldmatrix.sync.aligned.m8n8.x4.shared.b16 {%0,%1,%2,%3}, [%4];" \
        : "=r"(r0),"=r"(r1),"=r"(r2),"=r"(r3) : "r"(addr))
#define MMA16816(c0,c1,c2,c3,a0,a1,a2,a3,b0,b1) \
    asm volatile("mma.sync.aligned.m16n8k16.row.col.f32.f16.f16.f32 " \
        "{%0,%1,%2,%3},{%4,%5,%6,%7},{%8,%9},{%0,%1,%2,%3};" \
        : "+f"(c0),"+f"(c1),"+f"(c2),"+f"(c3) \
        : "r"(a0),"r"(a1),"r"(a2),"r"(a3),"r"(b0),"r"(b1))

// ==================== split kernels ====================
__device__ __forceinline__ void split2h(float v, __half& h, __half& l) {
    h = __float2half_rn(v);
    l = __float2half_rn(v - __half2float(h));
}

__global__ __launch_bounds__(256) void split_x_kernel(
    const float* __restrict__ src, __half* __restrict__ hi,
    __half* __restrict__ lo, int n4)
{
    int i = blockIdx.x * blockDim.x + threadIdx.x;
    if (i >= n4) return;
    float4 v = ((const float4*)src)[i];
    __half h0,h1,h2,h3,l0,l1,l2,l3;
    split2h(v.x,h0,l0); split2h(v.y,h1,l1); split2h(v.z,h2,l2); split2h(v.w,h3,l3);
    __half2* hp = (__half2*)hi;
    __half2* lp = (__half2*)lo;
    hp[i*2]   = __half2(h0,h1);
    hp[i*2+1] = __half2(h2,h3);
    lp[i*2]   = __half2(l0,l1);
    lp[i*2+1] = __half2(l2,l3);
}

// transpose + split: Wt[n][k] = W[k][n]
__global__ __launch_bounds__(256) void wsplit_kernel(
    const float* __restrict__ W0, const float* __restrict__ W1,
    const float* __restrict__ W2, const float* __restrict__ W3,
    __half* __restrict__ wth, __half* __restrict__ wtl)
{
    int z = blockIdx.z;
    const float* W = (z == 0) ? W0 : (z == 1) ? W1 : (z == 2) ? W2 : W3;
    __half* ho = wth + (size_t)z * WSZ;
    __half* lo = wtl + (size_t)z * WSZ;
    __shared__ float t[32][33];
    int k0 = blockIdx.y * 32, n0 = blockIdx.x * 32;
    int tx = threadIdx.x & 31, ty = threadIdx.x >> 5;  // 32 x 8
    #pragma unroll
    for (int i = 0; i < 32; i += 8)
        t[ty + i][tx] = W[(size_t)(k0 + ty + i) * 1024 + n0 + tx];
    __syncthreads();
    #pragma unroll
    for (int i = 0; i < 32; i += 8) {
        float v = t[tx][ty + i];   // W[k0+tx][n0+ty+i]
        __half h, l;
        split2h(v, h, l);
        ho[(size_t)(n0 + ty + i) * 1024 + k0 + tx] = h;
        lo[(size_t)(n0 + ty + i) * 1024 + k0 + tx] = l;
    }
}

// ==================== mma.sync fp16 split-3 GEMM ====================
// C[8192 x 1024] = Ah@Bh^T + Al@Bh^T + Ah@Bl^T + bias (B stored [N,K])
// Tile 128x256, 8 warps (2x4), warp tile 64x64, BK=32, 4-stage cp.async.
#define TBM 128
#define TBN 256
#define TKC 32
#define NST 4
#define NVIT 96                          // 3 terms x 32 chunks
#define APITCH 40                        // halfs per row (+8 pad)
#define STG_A_BYTES (TBM * APITCH * 2)   // 10240
#define STG_B_BYTES (TBN * APITCH * 2)   // 20480
#define STG (STG_A_BYTES + STG_B_BYTES)  // 30720
#define GSMEM (NST * STG)                // 122880

__global__ __launch_bounds__(256, 1) void gemm3_kernel(
    const __half* __restrict__ Ah, const __half* __restrict__ Al,
    const __half* __restrict__ Wth, const __half* __restrict__ Wtl,
    const float* __restrict__ b0, const float* __restrict__ b1,
    const float* __restrict__ b2,
    float* __restrict__ C0, float* __restrict__ C1, float* __restrict__ C2,
    int normFlag)
{
    extern __shared__ __align__(128) char dsm[];
    const uint32_t sb = (uint32_t)__cvta_generic_to_shared(dsm);

    const int tid = threadIdx.x;
    const int lane = tid & 31;
    const int wid = tid >> 5;
    const int wm = wid & 1;        // 0..1 -> M (64 rows each)
    const int wn = wid >> 1;       // 0..3 -> N (64 cols each)
    const int z = blockIdx.z;
    const int row0 = blockIdx.y * TBM;
    const int col0 = blockIdx.x * TBN;

    const __half* Bh = Wth + (size_t)z * WSZ;
    const __half* Bl = Wtl + (size_t)z * WSZ;
    const float* bias = (z == 0) ? b0 : (z == 1) ? b1 : b2;
    float* C = (z == 0) ? C0 : (z == 1) ? C1 : C2;

    // cp.async addressing
    const int a_r  = tid >> 2;            // for A: +i*64 rows
    const int a_cc = (tid & 3) * 8;
    const uint32_t a_dst0 = (uint32_t)((a_r * APITCH + a_cc) * 2);
    const int b_r  = tid >> 2;            // for B: +i*64 rows
    const int b_cc = (tid & 3) * 8;
    const uint32_t b_dst0 = (uint32_t)(STG_A_BYTES + (b_r * APITCH + b_cc) * 2);

    auto issue = [&](int kv) {
        const int term = kv >> 5;
        const int kk = (kv & 31) * TKC;
        const __half* At = (term == 1) ? Al : Ah;
        const __half* Bt = (term == 2) ? Bl : Bh;
        const uint32_t st = sb + (kv & (NST - 1)) * STG;
        #pragma unroll
        for (int i = 0; i < 2; i++) {
            uint32_t d = st + a_dst0 + i * 64 * APITCH * 2;
            CP_ASYNC16(d, At + (size_t)(row0 + a_r + i * 64) * 1024 + kk + a_cc);
        }
        #pragma unroll
        for (int i = 0; i < 4; i++) {
            uint32_t d = st + b_dst0 + i * 64 * APITCH * 2;
            CP_ASYNC16(d, Bt + (size_t)(col0 + b_r + i * 64) * 1024 + kk + b_cc);
        }
    };

    // ldmatrix lane addressing (byte offsets, stage-relative)
    const int lrow = ((lane >> 3) & 1) * 8 + (lane & 7);
    const int lcol = (lane >> 4) * 8;
    uint32_t a_base[4], b_base[4];
    #pragma unroll
    for (int i = 0; i < 4; i++)
        a_base[i] = (uint32_t)(((wm * 64 + i * 16 + lrow) * APITCH + lcol) * 2);
    #pragma unroll
    for (int j2 = 0; j2 < 4; j2++)
        b_base[j2] = (uint32_t)(STG_A_BYTES +
                     ((wn * 64 + j2 * 16 + lrow) * APITCH + lcol) * 2);

    float c[4][8][4];
    #pragma unroll
    for (int i = 0; i < 4; i++)
        #pragma unroll
        for (int j = 0; j < 8; j++)
            #pragma unroll
            for (int r = 0; r < 4; r++) c[i][j][r] = 0.f;

    issue(0); CP_COMMIT();
    issue(1); CP_COMMIT();
    issue(2); CP_COMMIT();

    for (int kv = 0; kv < NVIT; kv++) {
        CP_WAIT2();
        __syncthreads();
        if (kv + 3 < NVIT) issue(kv + 3);
        CP_COMMIT();
        const uint32_t st = sb + (kv & (NST - 1)) * STG;
        #pragma unroll
        for (int ks = 0; ks < 2; ks++) {
            const uint32_t ko = (uint32_t)(ks * 16 * 2);
            uint32_t a[4][4];
            #pragma unroll
            for (int i = 0; i < 4; i++)
                LDMATRIX_X4(a[i][0], a[i][1], a[i][2], a[i][3], st + a_base[i] + ko);
            uint32_t b[4][4];
            #pragma unroll
            for (int j2 = 0; j2 < 4; j2++)
                LDMATRIX_X4(b[j2][0], b[j2][1], b[j2][2], b[j2][3], st + b_base[j2] + ko);
            #pragma unroll
            for (int i = 0; i < 4; i++)
                #pragma unroll
                for (int j = 0; j < 8; j++) {
                    const int j2 = j >> 1, hi = j & 1;
                    MMA16816(c[i][j][0], c[i][j][1], c[i][j][2], c[i][j][3],
                             a[i][0], a[i][1], a[i][2], a[i][3],
                             b[j2][hi], b[j2][2 + hi]);
                }
        }
    }

    // ---------------- epilogue: bias + optional per-head L2 norm ----------------
    const int groupID = lane >> 2;
    const int tig = lane & 3;
    const bool doNorm = (z < normFlag);

    // bias per j (col pair), independent of i
    float bj0[8], bj1[8];
    #pragma unroll
    for (int j = 0; j < 8; j++) {
        int col = col0 + wn * 64 + j * 8 + tig * 2;
        bj0[j] = bias[col];
        bj1[j] = bias[col + 1];
    }
    #pragma unroll
    for (int i = 0; i < 4; i++)
        #pragma unroll
        for (int j = 0; j < 8; j++) {
            c[i][j][0] += bj0[j]; c[i][j][1] += bj1[j];
            c[i][j][2] += bj0[j]; c[i][j][3] += bj1[j];
        }

    if (doNorm) {
        // head = this warp's 64-col span; reduce across the 4-lane quad
        #pragma unroll
        for (int i = 0; i < 4; i++) {
            #pragma unroll
            for (int hf = 0; hf < 2; hf++) {
                float ss = 0.f;
                #pragma unroll
                for (int j = 0; j < 8; j++)
                    ss += c[i][j][2*hf] * c[i][j][2*hf] +
                          c[i][j][2*hf+1] * c[i][j][2*hf+1];
                ss += __shfl_xor_sync(0xFFFFFFFFu, ss, 1);
                ss += __shfl_xor_sync(0xFFFFFFFFu, ss, 2);
                float inv = 1.f / fmaxf(sqrtf(ss), 1e-12f);
                #pragma unroll
                for (int j = 0; j < 8; j++) {
                    c[i][j][2*hf]   *= inv;
                    c[i][j][2*hf+1] *= inv;
                }
            }
        }
    }

    #pragma unroll
    for (int i = 0; i < 4; i++) {
        int row = row0 + wm * 64 + i * 16 + groupID;
        #pragma unroll
        for (int j = 0; j < 8; j++) {
            int col = col0 + wn * 64 + j * 8 + tig * 2;
            *(float2*)(C + (size_t)row * 1024 + col) =
                make_float2(c[i][j][0], c[i][j][1]);
            *(float2*)(C + (size_t)(row + 8) * 1024 + col) =
                make_float2(c[i][j][2], c[i][j][3]);
        }
    }
}

// ==================== K^T V partial (fp32) ====================
__global__ __launch_bounds__(256) void ktv_partial_kernel(
    const float* __restrict__ k, const float* __restrict__ v,
    float* __restrict__ Sp)
{
    int blk = blockIdx.x;          // 0..511
    int bh = blk >> 3;
    int chunk = blk & 7;
    int b = bh >> 4, h = bh & 15;
    const float* kb = k + (size_t)b * NTOK * FEATS + h * HDIM;
    const float* vb = v + (size_t)b * NTOK * FEATS + h * HDIM;

    __shared__ float ks[32][HDIM];
    __shared__ float vs[32][HDIM];

    int tid = threadIdx.x;
    int p  = tid >> 2;
    int qb = (tid & 3) * 16;

    float acc[16];
    #pragma unroll
    for (int i = 0; i < 16; i++) acc[i] = 0.f;

    int t0 = chunk * 256;
    for (int j0 = t0; j0 < t0 + 256; j0 += 32) {
        #pragma unroll
        for (int i = tid; i < 32 * HDIM; i += 256) {
            int r = i >> 6, cc = i & 63;
            ks[r][cc] = kb[(size_t)(j0 + r) * FEATS + cc];
            vs[r][cc] = vb[(size_t)(j0 + r) * FEATS + cc];
        }
        __syncthreads();
        #pragma unroll 4
        for (int j = 0; j < 32; j++) {
            float kp = ks[j][p];
            #pragma unroll
            for (int i = 0; i < 16; i++)
                acc[i] = fmaf(kp, vs[j][qb + i], acc[i]);
        }
        __syncthreads();
    }
    float* Sb = Sp + ((size_t)bh * 8 + chunk) * HDIM * HDIM;
    #pragma unroll
    for (int i = 0; i < 16; i++)
        Sb[p * HDIM + qb + i] = acc[i];
}

__global__ __launch_bounds__(256) void ktv_reduce_kernel(
    const float* __restrict__ Sp, const float* __restrict__ m,
    float* __restrict__ S)
{
    int bh = blockIdx.x;
    int h = bh & 15;
    float sig = 1.f / (1.f + expf(-m[h]));
    float inv = 1.f / powf((float)NTOK, sig);
    const float* base = Sp + (size_t)bh * 8 * HDIM * HDIM;
    float* out = S + (size_t)bh * HDIM * HDIM;
    for (int e = threadIdx.x; e < HDIM * HDIM; e += 256) {
        float s = 0.f;
        #pragma unroll
        for (int c = 0; c < 8; c++) s += base[c * HDIM * HDIM + e];
        out[e] = s * inv;
    }
}

// ==================== attn = Q @ S ; fp16 hi/lo output ====================
__global__ __launch_bounds__(256) void qs_kernel(
    const float* __restrict__ q, const float* __restrict__ S,
    __half* __restrict__ ah, __half* __restrict__ al)
{
    int bh = blockIdx.y;
    int b = bh >> 4, h = bh & 15;
    int row0 = blockIdx.x * 64;

    __shared__ float Ss[HDIM][HDIM];
    __shared__ float qsm[64][HDIM + 1];

    const float* qb = q + (size_t)b * NTOK * FEATS + h * HDIM;
    const float* Sb = S + (size_t)bh * HDIM * HDIM;

    int tid = threadIdx.x;
    #pragma unroll
    for (int i = tid; i < 64 * 64; i += 256) {
        int r = i >> 6, cc = i & 63;
        Ss[r][cc] = Sb[i];
        qsm[r][cc] = qb[(size_t)(row0 + r) * FEATS + cc];
    }
    __syncthreads();

    int c  = tid & 63;
    int r0 = tid >> 6;
    #pragma unroll
    for (int i = 0; i < 16; i++) {
        int r = i * 4 + r0;
        float acc = 0.f;
        #pragma unroll
        for (int pp = 0; pp < HDIM; pp++)
            acc = fmaf(qsm[r][pp], Ss[pp][c], acc);
        size_t off = (size_t)(b * NTOK + row0 + r) * FEATS + h * HDIM + c;
        __half hh, ll;
        split2h(acc, hh, ll);
        ah[off] = hh;
        al[off] = ll;
    }
}

// ==================== launch ====================
extern "C" void kernel_launch(void* const* d_in, const int* in_sizes, int n_in,
                              void* d_out, int out_size)
{
    const float* x  = (const float*)d_in[0];
    const float* Wq = (const float*)d_in[1];
    const float* bq = (const float*)d_in[2];
    const float* Wk = (const float*)d_in[3];
    const float* bk = (const float*)d_in[4];
    const float* Wv = (const float*)d_in[5];
    const float* bv = (const float*)d_in[6];
    const float* Wo = (const float*)d_in[7];
    const float* bo = (const float*)d_in[8];
    const float* m  = (const float*)d_in[9];
    float* out = (float*)d_out;

    float *q, *k, *v, *S, *Sp;
    __half *xh, *xl, *ah, *al, *wth, *wtl;
    cudaGetSymbolAddress((void**)&q, g_q);
    cudaGetSymbolAddress((void**)&k, g_k);
    cudaGetSymbolAddress((void**)&v, g_v);
    cudaGetSymbolAddress((void**)&S, g_S);
    cudaGetSymbolAddress((void**)&Sp, g_Sp);
    cudaGetSymbolAddress((void**)&xh, g_xh);
    cudaGetSymbolAddress((void**)&xl, g_xl);
    cudaGetSymbolAddress((void**)&ah, g_ah);
    cudaGetSymbolAddress((void**)&al, g_al);
    cudaGetSymbolAddress((void**)&wth, g_wth);
    cudaGetSymbolAddress((void**)&wtl, g_wtl);

    cudaFuncSetAttribute(gemm3_kernel,
                         cudaFuncAttributeMaxDynamicSharedMemorySize, GSMEM);

    // splits
    split_x_kernel<<<MROWS * FEATS / 4 / 256, 256>>>(x, xh, xl, MROWS * FEATS / 4);
    wsplit_kernel<<<dim3(32, 32, 4), 256>>>(Wq, Wk, Wv, Wo, wth, wtl);

    // fused QKV projections + bias + Q/K L2 norm
    gemm3_kernel<<<dim3(1024 / TBN, MROWS / TBM, 3), 256, GSMEM>>>(
        xh, xl, wth, wtl, bq, bk, bv, q, k, v, 2);

    ktv_partial_kernel<<<512, 256>>>(k, v, Sp);
    ktv_reduce_kernel<<<64, 256>>>(Sp, m, S);

    qs_kernel<<<dim3(NTOK / 64, 64), 256>>>(q, S, ah, al);

    // output projection
    gemm3_kernel<<<dim3(1024 / TBN, MROWS / TBM, 1), 256, GSMEM>>>(
        ah, al, wth + 3 * (size_t)WSZ, wtl + 3 * (size_t)WSZ,
        bo, bo, bo, out, out, out, 0);
}

// round 5
// speedup vs baseline: 1.8693x; 1.8693x over previous
#include <cuda_runtime.h>
#include <cuda_fp16.h>
#include <math.h>
#include <stdint.h>

// Problem constants
#define BATCH 4
#define NTOK  2048
#define FEATS 1024
#define NHEAD 16
#define HDIM  64
#define MROWS (BATCH * NTOK)   // 8192
#define WSZ   (1024 * 1024)

// ---------------- scratch (device globals) ----------------
__device__ float g_q[MROWS * FEATS];
__device__ float g_k[MROWS * FEATS];
__device__ float g_v[MROWS * FEATS];
__device__ float g_S[64 * HDIM * HDIM];
__device__ float g_Sp[512 * HDIM * HDIM];
__device__ __half g_xh[MROWS * FEATS];
__device__ __half g_xl[MROWS * FEATS];
__device__ __half g_ah[MROWS * FEATS];
__device__ __half g_al[MROWS * FEATS];
__device__ __half g_wth[4 * WSZ];   // W^T hi [N,K] per matrix (fp16)

// ==================== PTX helpers ====================
#define CP_ASYNC16(dst, src) \
    asm volatile("cp.async.cg.shared.global [%0], [%1], 16;\n" :: "r"(dst), "l"(src))
#define CP_COMMIT() asm volatile("cp.async.commit_group;\n")
#define CP_WAIT1()  asm volatile("cp.async.wait_group 1;\n" ::: "memory")

#define LDMATRIX_X4(r0,r1,r2,r3,addr) \
    asm volatile("ldmatrix.sync.aligned.m8n8.x4.shared.b16 {%0,%1,%2,%3}, [%4];" \
        : "=r"(r0),"=r"(r1),"=r"(r2),"=r"(r3) : "r"(addr))
#define MMA16816(c0,c1,c2,c3,a0,a1,a2,a3,b0,b1) \
    asm volatile("mma.sync.aligned.m16n8k16.row.col.f32.f16.f16.f32 " \
        "{%0,%1,%2,%3},{%4,%5,%6,%7},{%8,%9},{%0,%1,%2,%3};" \
        : "+f"(c0),"+f"(c1),"+f"(c2),"+f"(c3) \
        : "r"(a0),"r"(a1),"r"(a2),"r"(a3),"r"(b0),"r"(b1))

// ==================== split kernels ====================
__device__ __forceinline__ void split2h(float v, __half& h, __half& l) {
    h = __float2half_rn(v);
    l = __float2half_rn(v - __half2float(h));
}

__global__ __launch_bounds__(256) void split_x_kernel(
    const float* __restrict__ src, __half* __restrict__ hi,
    __half* __restrict__ lo, int n4)
{
    int i = blockIdx.x * blockDim.x + threadIdx.x;
    if (i >= n4) return;
    float4 v = ((const float4*)src)[i];
    __half h0,h1,h2,h3,l0,l1,l2,l3;
    split2h(v.x,h0,l0); split2h(v.y,h1,l1); split2h(v.z,h2,l2); split2h(v.w,h3,l3);
    __half2* hp = (__half2*)hi;
    __half2* lp = (__half2*)lo;
    hp[i*2]   = __half2(h0,h1);
    hp[i*2+1] = __half2(h2,h3);
    lp[i*2]   = __half2(l0,l1);
    lp[i*2+1] = __half2(l2,l3);
}

// transpose + fp16: Wt[n][k] = fp16(W[k][n])
__global__ __launch_bounds__(256) void wsplit_kernel(
    const float* __restrict__ W0, const float* __restrict__ W1,
    const float* __restrict__ W2, const float* __restrict__ W3,
    __half* __restrict__ wth)
{
    int z = blockIdx.z;
    const float* W = (z == 0) ? W0 : (z == 1) ? W1 : (z == 2) ? W2 : W3;
    __half* ho = wth + (size_t)z * WSZ;
    __shared__ float t[32][33];
    int k0 = blockIdx.y * 32, n0 = blockIdx.x * 32;
    int tx = threadIdx.x & 31, ty = threadIdx.x >> 5;  // 32 x 8
    #pragma unroll
    for (int i = 0; i < 32; i += 8)
        t[ty + i][tx] = W[(size_t)(k0 + ty + i) * 1024 + n0 + tx];
    __syncthreads();
    #pragma unroll
    for (int i = 0; i < 32; i += 8)
        ho[(size_t)(n0 + ty + i) * 1024 + k0 + tx] = __float2half_rn(t[tx][ty + i]);
}

// ==================== mma.sync fp16 2-term GEMM ====================
// C = (Ah + Al) @ Bh^T + bias  (B stored [N,K] fp16)
// Tile 128x128, 8 warps (2M x 4N), warp tile 64x32, chunk K=32, 3-stage.
#define TBM 128
#define TBN 128
#define TKC 32
#define NCH 32
#define APITCH 40
#define TILE_B (128 * APITCH * 2)   // 10240 bytes per tile
#define STG (3 * TILE_B)            // 30720 (Ah, Al, Bh)
#define GSMEM (3 * STG)             // 92160

__global__ __launch_bounds__(256, 2) void gemm2_kernel(
    const __half* __restrict__ Ah, const __half* __restrict__ Al,
    const __half* __restrict__ Wth,
    const float* __restrict__ b0, const float* __restrict__ b1,
    const float* __restrict__ b2,
    float* __restrict__ C0, float* __restrict__ C1, float* __restrict__ C2,
    int normFlag)
{
    extern __shared__ __align__(128) char dsm[];
    const uint32_t sb = (uint32_t)__cvta_generic_to_shared(dsm);

    const int tid = threadIdx.x;
    const int lane = tid & 31;
    const int wid = tid >> 5;
    const int wm = wid & 1;        // 0..1 -> 64-row half
    const int wn = wid >> 1;       // 0..3 -> 32-col quarter
    const int z = blockIdx.z;
    const int row0 = blockIdx.y * TBM;
    const int col0 = blockIdx.x * TBN;

    const __half* Bh = Wth + (size_t)z * WSZ;
    const float* bias = (z == 0) ? b0 : (z == 1) ? b1 : b2;
    float* C = (z == 0) ? C0 : (z == 1) ? C1 : C2;

    // cp.async addressing: r covers 64 rows per pass, 2 passes per tile
    const int ld_r  = tid >> 2;
    const int ld_c  = (tid & 3) * 8;          // half offset within 32-wide chunk
    const uint32_t ld_dst = (uint32_t)((ld_r * APITCH + ld_c) * 2);

    auto issue = [&](int c) {
        const int kk = c * TKC;
        const uint32_t st = sb + (c % 3) * STG;
        #pragma unroll
        for (int i = 0; i < 2; i++) {
            uint32_t d = st + ld_dst + i * 64 * APITCH * 2;
            const size_t g = (size_t)(row0 + ld_r + i * 64) * 1024 + kk + ld_c;
            CP_ASYNC16(d, Ah + g);
            CP_ASYNC16(d + TILE_B, Al + g);
            CP_ASYNC16(d + 2 * TILE_B,
                       Bh + (size_t)(col0 + ld_r + i * 64) * 1024 + kk + ld_c);
        }
    };

    // ldmatrix lane addressing (byte offsets, stage-relative)
    const int lrow = ((lane >> 3) & 1) * 8 + (lane & 7);
    const int lcol = (lane >> 4) * 8;
    uint32_t a_base[4], b_base[2];
    #pragma unroll
    for (int i = 0; i < 4; i++)
        a_base[i] = (uint32_t)(((wm * 64 + i * 16 + lrow) * APITCH + lcol) * 2);
    #pragma unroll
    for (int j2 = 0; j2 < 2; j2++)
        b_base[j2] = (uint32_t)(2 * TILE_B +
                     ((wn * 32 + j2 * 16 + lrow) * APITCH + lcol) * 2);

    float c[4][4][4];
    #pragma unroll
    for (int i = 0; i < 4; i++)
        #pragma unroll
        for (int j = 0; j < 4; j++)
            #pragma unroll
            for (int r = 0; r < 4; r++) c[i][j][r] = 0.f;

    issue(0); CP_COMMIT();
    issue(1); CP_COMMIT();

    for (int ch = 0; ch < NCH; ch++) {
        CP_WAIT1();
        __syncthreads();
        const uint32_t st = sb + (ch % 3) * STG;
        #pragma unroll
        for (int ks = 0; ks < 2; ks++) {
            const uint32_t ko = (uint32_t)(ks * 16 * 2);
            uint32_t b[2][4];
            #pragma unroll
            for (int j2 = 0; j2 < 2; j2++)
                LDMATRIX_X4(b[j2][0], b[j2][1], b[j2][2], b[j2][3],
                            st + b_base[j2] + ko);
            uint32_t a[4][4];
            // hi term
            #pragma unroll
            for (int i = 0; i < 4; i++)
                LDMATRIX_X4(a[i][0], a[i][1], a[i][2], a[i][3],
                            st + a_base[i] + ko);
            #pragma unroll
            for (int i = 0; i < 4; i++)
                #pragma unroll
                for (int j = 0; j < 4; j++) {
                    const int j2 = j >> 1, hi = j & 1;
                    MMA16816(c[i][j][0], c[i][j][1], c[i][j][2], c[i][j][3],
                             a[i][0], a[i][1], a[i][2], a[i][3],
                             b[j2][hi], b[j2][2 + hi]);
                }
            // lo term (reuse B fragments)
            #pragma unroll
            for (int i = 0; i < 4; i++)
                LDMATRIX_X4(a[i][0], a[i][1], a[i][2], a[i][3],
                            st + TILE_B + a_base[i] + ko);
            #pragma unroll
            for (int i = 0; i < 4; i++)
                #pragma unroll
                for (int j = 0; j < 4; j++) {
                    const int j2 = j >> 1, hi = j & 1;
                    MMA16816(c[i][j][0], c[i][j][1], c[i][j][2], c[i][j][3],
                             a[i][0], a[i][1], a[i][2], a[i][3],
                             b[j2][hi], b[j2][2 + hi]);
                }
        }
        if (ch + 2 < NCH) issue(ch + 2);
        CP_COMMIT();
    }

    // ---------------- epilogue: bias + optional per-head L2 norm ----------------
    const int groupID = lane >> 2;
    const int tig = lane & 3;

    #pragma unroll
    for (int j = 0; j < 4; j++) {
        int col = col0 + wn * 32 + j * 8 + tig * 2;
        float bb0 = bias[col], bb1 = bias[col + 1];
        #pragma unroll
        for (int i = 0; i < 4; i++) {
            c[i][j][0] += bb0; c[i][j][1] += bb1;
            c[i][j][2] += bb0; c[i][j][3] += bb1;
        }
    }

    if (z < normFlag) {
        // head = 64 cols = two adjacent wn quarters (wn ^ 1 is the partner)
        float* ssm = (float*)dsm;   // [4 wn][128 rows]
        float ssq[4][2];
        #pragma unroll
        for (int i = 0; i < 4; i++)
            #pragma unroll
            for (int hf = 0; hf < 2; hf++) {
                float ss = 0.f;
                #pragma unroll
                for (int j = 0; j < 4; j++)
                    ss += c[i][j][2*hf] * c[i][j][2*hf]
                        + c[i][j][2*hf+1] * c[i][j][2*hf+1];
                ss += __shfl_xor_sync(0xFFFFFFFFu, ss, 1);
                ss += __shfl_xor_sync(0xFFFFFFFFu, ss, 2);
                ssq[i][hf] = ss;   // sum over this warp's 32 cols for row
            }
        __syncthreads();   // ensure smem tiles no longer needed
        if (tig == 0) {
            #pragma unroll
            for (int i = 0; i < 4; i++)
                #pragma unroll
                for (int hf = 0; hf < 2; hf++)
                    ssm[wn * 128 + wm * 64 + i * 16 + groupID + hf * 8] = ssq[i][hf];
        }
        __syncthreads();
        #pragma unroll
        for (int i = 0; i < 4; i++)
            #pragma unroll
            for (int hf = 0; hf < 2; hf++) {
                int row = wm * 64 + i * 16 + groupID + hf * 8;
                float tot = ssq[i][hf] + ssm[(wn ^ 1) * 128 + row];
                float inv = 1.f / fmaxf(sqrtf(tot), 1e-12f);
                #pragma unroll
                for (int j = 0; j < 4; j++) {
                    c[i][j][2*hf]   *= inv;
                    c[i][j][2*hf+1] *= inv;
                }
            }
    }

    #pragma unroll
    for (int i = 0; i < 4; i++) {
        int row = row0 + wm * 64 + i * 16 + groupID;
        #pragma unroll
        for (int j = 0; j < 4; j++) {
            int col = col0 + wn * 32 + j * 8 + tig * 2;
            *(float2*)(C + (size_t)row * 1024 + col) =
                make_float2(c[i][j][0], c[i][j][1]);
            *(float2*)(C + (size_t)(row + 8) * 1024 + col) =
                make_float2(c[i][j][2], c[i][j][3]);
        }
    }
}

// ==================== K^T V partial: 4x4 register tile ====================
__global__ __launch_bounds__(256) void ktv_partial_kernel(
    const float* __restrict__ k, const float* __restrict__ v,
    float* __restrict__ Sp)
{
    int blk = blockIdx.x;          // 0..511
    int bh = blk >> 3;
    int chunk = blk & 7;
    int b = bh >> 4, h = bh & 15;
    const float* kb = k + (size_t)b * NTOK * FEATS + h * HDIM;
    const float* vb = v + (size_t)b * NTOK * FEATS + h * HDIM;

    __shared__ float ks[32][HDIM];
    __shared__ float vs[32][HDIM];

    int tid = threadIdx.x;
    int ty = tid >> 4;             // 0..15 -> S rows p = ty*4..+3
    int tx = tid & 15;             // 0..15 -> S cols q = tx*4..+3

    float acc[4][4];
    #pragma unroll
    for (int a = 0; a < 4; a++)
        #pragma unroll
        for (int bq = 0; bq < 4; bq++) acc[a][bq] = 0.f;

    int t0 = chunk * 256;
    for (int j0 = t0; j0 < t0 + 256; j0 += 32) {
        // load 32 rows x 64 floats of K and V (float4, coalesced)
        #pragma unroll
        for (int ppp = 0; ppp < 2; ppp++) {
            int r = (tid >> 4) + ppp * 16;
            int cc = (tid & 15) * 4;
            *(float4*)&ks[r][cc] = *(const float4*)(kb + (size_t)(j0 + r) * FEATS + cc);
            *(float4*)&vs[r][cc] = *(const float4*)(vb + (size_t)(j0 + r) * FEATS + cc);
        }
        __syncthreads();
        #pragma unroll 8
        for (int j = 0; j < 32; j++) {
            float4 kv = *(float4*)&ks[j][ty * 4];
            float4 vv = *(float4*)&vs[j][tx * 4];
            float kr[4] = {kv.x, kv.y, kv.z, kv.w};
            float vr[4] = {vv.x, vv.y, vv.z, vv.w};
            #pragma unroll
            for (int a = 0; a < 4; a++)
                #pragma unroll
                for (int bq = 0; bq < 4; bq++)
                    acc[a][bq] = fmaf(kr[a], vr[bq], acc[a][bq]);
        }
        __syncthreads();
    }
    float* Sb = Sp + ((size_t)bh * 8 + chunk) * HDIM * HDIM;
    #pragma unroll
    for (int a = 0; a < 4; a++)
        *(float4*)(Sb + (ty * 4 + a) * HDIM + tx * 4) =
            make_float4(acc[a][0], acc[a][1], acc[a][2], acc[a][3]);
}

__global__ __launch_bounds__(256) void ktv_reduce_kernel(
    const float* __restrict__ Sp, const float* __restrict__ m,
    float* __restrict__ S)
{
    int bh = blockIdx.x;
    int h = bh & 15;
    float sig = 1.f / (1.f + expf(-m[h]));
    float inv = 1.f / powf((float)NTOK, sig);
    const float* base = Sp + (size_t)bh * 8 * HDIM * HDIM;
    float* out = S + (size_t)bh * HDIM * HDIM;
    for (int e = threadIdx.x; e < HDIM * HDIM; e += 256) {
        float s = 0.f;
        #pragma unroll
        for (int c = 0; c < 8; c++) s += base[c * HDIM * HDIM + e];
        out[e] = s * inv;
    }
}

// ==================== attn = Q @ S ; fp16 hi/lo output (4x4 tile) ====================
__global__ __launch_bounds__(256) void qs_kernel(
    const float* __restrict__ q, const float* __restrict__ S,
    __half* __restrict__ ah, __half* __restrict__ al)
{
    int bh = blockIdx.y;
    int b = bh >> 4, h = bh & 15;
    int row0 = blockIdx.x * 64;

    __shared__ float qT[HDIM][68];   // qT[d][token]
    __shared__ float Ss[HDIM][68];   // Ss[d][col]

    const float* qb = q + (size_t)b * NTOK * FEATS + h * HDIM;
    const float* Sb = S + (size_t)bh * HDIM * HDIM;

    int tid = threadIdx.x;
    for (int i = tid; i < HDIM * HDIM; i += 256) {
        int r = i >> 6, cc = i & 63;
        Ss[r][cc] = Sb[i];
    }
    for (int u = tid; u < 64 * 16; u += 256) {
        int t = u >> 4, d0 = (u & 15) * 4;
        float4 vv = *(const float4*)(qb + (size_t)(row0 + t) * FEATS + d0);
        qT[d0 + 0][t] = vv.x;
        qT[d0 + 1][t] = vv.y;
        qT[d0 + 2][t] = vv.z;
        qT[d0 + 3][t] = vv.w;
    }
    __syncthreads();

    int ty = tid >> 4;   // token group: rows row0 + ty*4..+3
    int tx = tid & 15;   // col group: cols tx*4..+3

    float acc[4][4];
    #pragma unroll
    for (int a = 0; a < 4; a++)
        #pragma unroll
        for (int bq = 0; bq < 4; bq++) acc[a][bq] = 0.f;

    #pragma unroll 8
    for (int pp = 0; pp < HDIM; pp++) {
        float4 qv = *(float4*)&qT[pp][ty * 4];
        float4 sv = *(float4*)&Ss[pp][tx * 4];
        float qr[4] = {qv.x, qv.y, qv.z, qv.w};
        float sr[4] = {sv.x, sv.y, sv.z, sv.w};
        #pragma unroll
        for (int a = 0; a < 4; a++)
            #pragma unroll
            for (int bq = 0; bq < 4; bq++)
                acc[a][bq] = fmaf(qr[a], sr[bq], acc[a][bq]);
    }

    #pragma unroll
    for (int a = 0; a < 4; a++) {
        size_t off = (size_t)(b * NTOK + row0 + ty * 4 + a) * FEATS + h * HDIM + tx * 4;
        __half2 hv[2], lv[2];
        #pragma unroll
        for (int p = 0; p < 2; p++) {
            __half h0, l0, h1, l1;
            split2h(acc[a][2*p],   h0, l0);
            split2h(acc[a][2*p+1], h1, l1);
            hv[p] = __half2(h0, h1);
            lv[p] = __half2(l0, l1);
        }
        *(__half2*)(ah + off)     = hv[0];
        *(__half2*)(ah + off + 2) = hv[1];
        *(__half2*)(al + off)     = lv[0];
        *(__half2*)(al + off + 2) = lv[1];
    }
}

// ==================== launch ====================
extern "C" void kernel_launch(void* const* d_in, const int* in_sizes, int n_in,
                              void* d_out, int out_size)
{
    const float* x  = (const float*)d_in[0];
    const float* Wq = (const float*)d_in[1];
    const float* bq = (const float*)d_in[2];
    const float* Wk = (const float*)d_in[3];
    const float* bk = (const float*)d_in[4];
    const float* Wv = (const float*)d_in[5];
    const float* bv = (const float*)d_in[6];
    const float* Wo = (const float*)d_in[7];
    const float* bo = (const float*)d_in[8];
    const float* m  = (const float*)d_in[9];
    float* out = (float*)d_out;

    float *q, *k, *v, *S, *Sp;
    __half *xh, *xl, *ah, *al, *wth;
    cudaGetSymbolAddress((void**)&q, g_q);
    cudaGetSymbolAddress((void**)&k, g_k);
    cudaGetSymbolAddress((void**)&v, g_v);
    cudaGetSymbolAddress((void**)&S, g_S);
    cudaGetSymbolAddress((void**)&Sp, g_Sp);
    cudaGetSymbolAddress((void**)&xh, g_xh);
    cudaGetSymbolAddress((void**)&xl, g_xl);
    cudaGetSymbolAddress((void**)&ah, g_ah);
    cudaGetSymbolAddress((void**)&al, g_al);
    cudaGetSymbolAddress((void**)&wth, g_wth);

    cudaFuncSetAttribute(gemm2_kernel,
                         cudaFuncAttributeMaxDynamicSharedMemorySize, GSMEM);

    // splits
    split_x_kernel<<<MROWS * FEATS / 4 / 256, 256>>>(x, xh, xl, MROWS * FEATS / 4);
    wsplit_kernel<<<dim3(32, 32, 4), 256>>>(Wq, Wk, Wv, Wo, wth);

    // fused QKV projections + bias + Q/K L2 norm
    gemm2_kernel<<<dim3(1024 / TBN, MROWS / TBM, 3), 256, GSMEM>>>(
        xh, xl, wth, bq, bk, bv, q, k, v, 2);

    ktv_partial_kernel<<<512, 256>>>(k, v, Sp);
    ktv_reduce_kernel<<<64, 256>>>(Sp, m, S);

    qs_kernel<<<dim3(NTOK / 64, 64), 256>>>(q, S, ah, al);

    // output projection
    gemm2_kernel<<<dim3(1024 / TBN, MROWS / TBM, 1), 256, GSMEM>>>(
        ah, al, wth + 3 * (size_t)WSZ,
        bo, bo, bo, out, out, out, 0);
}

// round 7
// speedup vs baseline: 3.0094x; 1.6099x over previous
#include <cuda_runtime.h>
#include <cuda_fp16.h>
#include <math.h>
#include <stdint.h>

// Problem constants
#define BATCH 4
#define NTOK  2048
#define FEATS 1024
#define NHEAD 16
#define HDIM  64
#define MROWS (BATCH * NTOK)   // 8192
#define WSZ   (1024 * 1024)

// ---------------- scratch (device globals) ----------------
__device__ float g_q[MROWS * FEATS];
__device__ float g_k[MROWS * FEATS];
__device__ float g_v[MROWS * FEATS];
__device__ float g_S[64 * HDIM * HDIM];
__device__ float g_Sp[512 * HDIM * HDIM];
__device__ __half g_xh[MROWS * FEATS];
__device__ __half g_ah[MROWS * FEATS];
__device__ __half g_wth[4 * WSZ];   // W^T [N,K] per matrix (fp16)

// ==================== PTX helpers ====================
#define CP_ASYNC16(dst, src) \
    asm volatile("cp.async.cg.shared.global [%0], [%1], 16;\n" :: "r"(dst), "l"(src))
#define CP_COMMIT() asm volatile("cp.async.commit_group;\n")
#define CP_WAIT2()  asm volatile("cp.async.wait_group 2;\n" ::: "memory")

#define LDMATRIX_X4(r0,r1,r2,r3,addr) \
    asm volatile("ldmatrix.sync.aligned.m8n8.x4.shared.b16 {%0,%1,%2,%3}, [%4];" \
        : "=r"(r0),"=r"(r1),"=r"(r2),"=r"(r3) : "r"(addr))
#define MMA16816(c0,c1,c2,c3,a0,a1,a2,a3,b0,b1) \
    asm volatile("mma.sync.aligned.m16n8k16.row.col.f32.f16.f16.f32 " \
        "{%0,%1,%2,%3},{%4,%5,%6,%7},{%8,%9},{%0,%1,%2,%3};" \
        : "+f"(c0),"+f"(c1),"+f"(c2),"+f"(c3) \
        : "r"(a0),"r"(a1),"r"(a2),"r"(a3),"r"(b0),"r"(b1))

// ==================== convert kernels ====================
__global__ __launch_bounds__(256) void tofp16_kernel(
    const float* __restrict__ src, __half* __restrict__ dst, int n4)
{
    int i = blockIdx.x * blockDim.x + threadIdx.x;
    if (i >= n4) return;
    float4 v = ((const float4*)src)[i];
    __half2* hp = (__half2*)dst;
    hp[i*2]   = __half2(__float2half_rn(v.x), __float2half_rn(v.y));
    hp[i*2+1] = __half2(__float2half_rn(v.z), __float2half_rn(v.w));
}

// transpose + fp16: Wt[n][k] = fp16(W[k][n])
__global__ __launch_bounds__(256) void wsplit_kernel(
    const float* __restrict__ W0, const float* __restrict__ W1,
    const float* __restrict__ W2, const float* __restrict__ W3,
    __half* __restrict__ wth)
{
    int z = blockIdx.z;
    const float* W = (z == 0) ? W0 : (z == 1) ? W1 : (z == 2) ? W2 : W3;
    __half* ho = wth + (size_t)z * WSZ;
    __shared__ float t[32][33];
    int k0 = blockIdx.y * 32, n0 = blockIdx.x * 32;
    int tx = threadIdx.x & 31, ty = threadIdx.x >> 5;  // 32 x 8
    #pragma unroll
    for (int i = 0; i < 32; i += 8)
        t[ty + i][tx] = W[(size_t)(k0 + ty + i) * 1024 + n0 + tx];
    __syncthreads();
    #pragma unroll
    for (int i = 0; i < 32; i += 8)
        ho[(size_t)(n0 + ty + i) * 1024 + k0 + tx] = __float2half_rn(t[tx][ty + i]);
}

// ==================== mma.sync fp16 single-term GEMM ====================
// C = A @ B^T + bias  (B stored [N,K] fp16)
// Tile 128x128, 8 warps (2M x 4N), warp tile 64x32, chunk K=32, 4-stage.
#define TBM 128
#define TBN 128
#define TKC 32
#define NCH 32
#define APITCH 40
#define TILE_B (128 * APITCH * 2)   // 10240 bytes per tile
#define STG (2 * TILE_B)            // 20480 (A, B)
#define NST 4
#define GSMEM (NST * STG)           // 81920

__global__ __launch_bounds__(256, 2) void gemm1_kernel(
    const __half* __restrict__ Ah, const __half* __restrict__ Wth,
    const float* __restrict__ b0, const float* __restrict__ b1,
    const float* __restrict__ b2,
    float* __restrict__ C0, float* __restrict__ C1, float* __restrict__ C2,
    int normFlag)
{
    extern __shared__ __align__(128) char dsm[];
    const uint32_t sb = (uint32_t)__cvta_generic_to_shared(dsm);

    const int tid = threadIdx.x;
    const int lane = tid & 31;
    const int wid = tid >> 5;
    const int wm = wid & 1;        // 0..1 -> 64-row half
    const int wn = wid >> 1;       // 0..3 -> 32-col quarter
    const int z = blockIdx.z;
    const int row0 = blockIdx.y * TBM;
    const int col0 = blockIdx.x * TBN;

    const __half* Bh = Wth + (size_t)z * WSZ;
    const float* bias = (z == 0) ? b0 : (z == 1) ? b1 : b2;
    float* C = (z == 0) ? C0 : (z == 1) ? C1 : C2;

    // cp.async addressing: r covers 64 rows per pass, 2 passes per tile
    const int ld_r  = tid >> 2;
    const int ld_c  = (tid & 3) * 8;
    const uint32_t ld_dst = (uint32_t)((ld_r * APITCH + ld_c) * 2);

    auto issue = [&](int c) {
        const int kk = c * TKC;
        const uint32_t st = sb + (c & (NST - 1)) * STG;
        #pragma unroll
        for (int i = 0; i < 2; i++) {
            uint32_t d = st + ld_dst + i * 64 * APITCH * 2;
            CP_ASYNC16(d, Ah + (size_t)(row0 + ld_r + i * 64) * 1024 + kk + ld_c);
            CP_ASYNC16(d + TILE_B,
                       Bh + (size_t)(col0 + ld_r + i * 64) * 1024 + kk + ld_c);
        }
    };

    // ldmatrix lane addressing (byte offsets, stage-relative)
    const int lrow = ((lane >> 3) & 1) * 8 + (lane & 7);
    const int lcol = (lane >> 4) * 8;
    uint32_t a_base[4], b_base[2];
    #pragma unroll
    for (int i = 0; i < 4; i++)
        a_base[i] = (uint32_t)(((wm * 64 + i * 16 + lrow) * APITCH + lcol) * 2);
    #pragma unroll
    for (int j2 = 0; j2 < 2; j2++)
        b_base[j2] = (uint32_t)(TILE_B +
                     ((wn * 32 + j2 * 16 + lrow) * APITCH + lcol) * 2);

    float c[4][4][4];
    #pragma unroll
    for (int i = 0; i < 4; i++)
        #pragma unroll
        for (int j = 0; j < 4; j++)
            #pragma unroll
            for (int r = 0; r < 4; r++) c[i][j][r] = 0.f;

    issue(0); CP_COMMIT();
    issue(1); CP_COMMIT();
    issue(2); CP_COMMIT();

    for (int ch = 0; ch < NCH; ch++) {
        CP_WAIT2();
        __syncthreads();
        const uint32_t st = sb + (ch & (NST - 1)) * STG;
        #pragma unroll
        for (int ks = 0; ks < 2; ks++) {
            const uint32_t ko = (uint32_t)(ks * 16 * 2);
            uint32_t b[2][4];
            #pragma unroll
            for (int j2 = 0; j2 < 2; j2++)
                LDMATRIX_X4(b[j2][0], b[j2][1], b[j2][2], b[j2][3],
                            st + b_base[j2] + ko);
            uint32_t a[4][4];
            #pragma unroll
            for (int i = 0; i < 4; i++)
                LDMATRIX_X4(a[i][0], a[i][1], a[i][2], a[i][3],
                            st + a_base[i] + ko);
            #pragma unroll
            for (int i = 0; i < 4; i++)
                #pragma unroll
                for (int j = 0; j < 4; j++) {
                    const int j2 = j >> 1, hi = j & 1;
                    MMA16816(c[i][j][0], c[i][j][1], c[i][j][2], c[i][j][3],
                             a[i][0], a[i][1], a[i][2], a[i][3],
                             b[j2][hi], b[j2][2 + hi]);
                }
        }
        if (ch + 3 < NCH) issue(ch + 3);
        CP_COMMIT();
    }

    // ---------------- epilogue: bias + optional per-head L2 norm ----------------
    const int groupID = lane >> 2;
    const int tig = lane & 3;

    #pragma unroll
    for (int j = 0; j < 4; j++) {
        int col = col0 + wn * 32 + j * 8 + tig * 2;
        float bb0 = bias[col], bb1 = bias[col + 1];
        #pragma unroll
        for (int i = 0; i < 4; i++) {
            c[i][j][0] += bb0; c[i][j][1] += bb1;
            c[i][j][2] += bb0; c[i][j][3] += bb1;
        }
    }

    if (z < normFlag) {
        // head = 64 cols = two adjacent wn quarters (wn ^ 1 is the partner)
        float* ssm = (float*)dsm;   // [4 wn][128 rows]
        float ssq[4][2];
        #pragma unroll
        for (int i = 0; i < 4; i++)
            #pragma unroll
            for (int hf = 0; hf < 2; hf++) {
                float ss = 0.f;
                #pragma unroll
                for (int j = 0; j < 4; j++)
                    ss += c[i][j][2*hf] * c[i][j][2*hf]
                        + c[i][j][2*hf+1] * c[i][j][2*hf+1];
                ss += __shfl_xor_sync(0xFFFFFFFFu, ss, 1);
                ss += __shfl_xor_sync(0xFFFFFFFFu, ss, 2);
                ssq[i][hf] = ss;
            }
        __syncthreads();
        if (tig == 0) {
            #pragma unroll
            for (int i = 0; i < 4; i++)
                #pragma unroll
                for (int hf = 0; hf < 2; hf++)
                    ssm[wn * 128 + wm * 64 + i * 16 + groupID + hf * 8] = ssq[i][hf];
        }
        __syncthreads();
        #pragma unroll
        for (int i = 0; i < 4; i++)
            #pragma unroll
            for (int hf = 0; hf < 2; hf++) {
                int row = wm * 64 + i * 16 + groupID + hf * 8;
                float tot = ssq[i][hf] + ssm[(wn ^ 1) * 128 + row];
                float inv = 1.f / fmaxf(sqrtf(tot), 1e-12f);
                #pragma unroll
                for (int j = 0; j < 4; j++) {
                    c[i][j][2*hf]   *= inv;
                    c[i][j][2*hf+1] *= inv;
                }
            }
    }

    #pragma unroll
    for (int i = 0; i < 4; i++) {
        int row = row0 + wm * 64 + i * 16 + groupID;
        #pragma unroll
        for (int j = 0; j < 4; j++) {
            int col = col0 + wn * 32 + j * 8 + tig * 2;
            *(float2*)(C + (size_t)row * 1024 + col) =
                make_float2(c[i][j][0], c[i][j][1]);
            *(float2*)(C + (size_t)(row + 8) * 1024 + col) =
                make_float2(c[i][j][2], c[i][j][3]);
        }
    }
}

// ==================== K^T V partial: 4x4 register tile ====================
__global__ __launch_bounds__(256) void ktv_partial_kernel(
    const float* __restrict__ k, const float* __restrict__ v,
    float* __restrict__ Sp)
{
    int blk = blockIdx.x;          // 0..511
    int bh = blk >> 3;
    int chunk = blk & 7;
    int b = bh >> 4, h = bh & 15;
    const float* kb = k + (size_t)b * NTOK * FEATS + h * HDIM;
    const float* vb = v + (size_t)b * NTOK * FEATS + h * HDIM;

    __shared__ float ks[32][HDIM];
    __shared__ float vs[32][HDIM];

    int tid = threadIdx.x;
    int ty = tid >> 4;
    int tx = tid & 15;

    float acc[4][4];
    #pragma unroll
    for (int a = 0; a < 4; a++)
        #pragma unroll
        for (int bq = 0; bq < 4; bq++) acc[a][bq] = 0.f;

    int t0 = chunk * 256;
    for (int j0 = t0; j0 < t0 + 256; j0 += 32) {
        #pragma unroll
        for (int ppp = 0; ppp < 2; ppp++) {
            int r = (tid >> 4) + ppp * 16;
            int cc = (tid & 15) * 4;
            *(float4*)&ks[r][cc] = *(const float4*)(kb + (size_t)(j0 + r) * FEATS + cc);
            *(float4*)&vs[r][cc] = *(const float4*)(vb + (size_t)(j0 + r) * FEATS + cc);
        }
        __syncthreads();
        #pragma unroll 8
        for (int j = 0; j < 32; j++) {
            float4 kv = *(float4*)&ks[j][ty * 4];
            float4 vv = *(float4*)&vs[j][tx * 4];
            float kr[4] = {kv.x, kv.y, kv.z, kv.w};
            float vr[4] = {vv.x, vv.y, vv.z, vv.w};
            #pragma unroll
            for (int a = 0; a < 4; a++)
                #pragma unroll
                for (int bq = 0; bq < 4; bq++)
                    acc[a][bq] = fmaf(kr[a], vr[bq], acc[a][bq]);
        }
        __syncthreads();
    }
    float* Sb = Sp + ((size_t)bh * 8 + chunk) * HDIM * HDIM;
    #pragma unroll
    for (int a = 0; a < 4; a++)
        *(float4*)(Sb + (ty * 4 + a) * HDIM + tx * 4) =
            make_float4(acc[a][0], acc[a][1], acc[a][2], acc[a][3]);
}

__global__ __launch_bounds__(256) void ktv_reduce_kernel(
    const float* __restrict__ Sp, const float* __restrict__ m,
    float* __restrict__ S)
{
    int bh = blockIdx.x;
    int h = bh & 15;
    float sig = 1.f / (1.f + expf(-m[h]));
    float inv = 1.f / powf((float)NTOK, sig);
    const float* base = Sp + (size_t)bh * 8 * HDIM * HDIM;
    float* out = S + (size_t)bh * HDIM * HDIM;
    for (int e = threadIdx.x; e < HDIM * HDIM; e += 256) {
        float s = 0.f;
        #pragma unroll
        for (int c = 0; c < 8; c++) s += base[c * HDIM * HDIM + e];
        out[e] = s * inv;
    }
}

// ==================== attn = Q @ S ; fp16 output (4x4 tile) ====================
__global__ __launch_bounds__(256) void qs_kernel(
    const float* __restrict__ q, const float* __restrict__ S,
    __half* __restrict__ ah)
{
    int bh = blockIdx.y;
    int b = bh >> 4, h = bh & 15;
    int row0 = blockIdx.x * 64;

    __shared__ float qT[HDIM][68];
    __shared__ float Ss[HDIM][68];

    const float* qb = q + (size_t)b * NTOK * FEATS + h * HDIM;
    const float* Sb = S + (size_t)bh * HDIM * HDIM;

    int tid = threadIdx.x;
    for (int i = tid; i < HDIM * HDIM; i += 256) {
        int r = i >> 6, cc = i & 63;
        Ss[r][cc] = Sb[i];
    }
    for (int u = tid; u < 64 * 16; u += 256) {
        int t = u >> 4, d0 = (u & 15) * 4;
        float4 vv = *(const float4*)(qb + (size_t)(row0 + t) * FEATS + d0);
        qT[d0 + 0][t] = vv.x;
        qT[d0 + 1][t] = vv.y;
        qT[d0 + 2][t] = vv.z;
        qT[d0 + 3][t] = vv.w;
    }
    __syncthreads();

    int ty = tid >> 4;
    int tx = tid & 15;

    float acc[4][4];
    #pragma unroll
    for (int a = 0; a < 4; a++)
        #pragma unroll
        for (int bq = 0; bq < 4; bq++) acc[a][bq] = 0.f;

    #pragma unroll 8
    for (int pp = 0; pp < HDIM; pp++) {
        float4 qv = *(float4*)&qT[pp][ty * 4];
        float4 sv = *(float4*)&Ss[pp][tx * 4];
        float qr[4] = {qv.x, qv.y, qv.z, qv.w};
        float sr[4] = {sv.x, sv.y, sv.z, sv.w};
        #pragma unroll
        for (int a = 0; a < 4; a++)
            #pragma unroll
            for (int bq = 0; bq < 4; bq++)
                acc[a][bq] = fmaf(qr[a], sr[bq], acc[a][bq]);
    }

    #pragma unroll
    for (int a = 0; a < 4; a++) {
        size_t off = (size_t)(b * NTOK + row0 + ty * 4 + a) * FEATS + h * HDIM + tx * 4;
        *(__half2*)(ah + off) =
            __half2(__float2half_rn(acc[a][0]), __float2half_rn(acc[a][1]));
        *(__half2*)(ah + off + 2) =
            __half2(__float2half_rn(acc[a][2]), __float2half_rn(acc[a][3]));
    }
}

// ==================== launch ====================
extern "C" void kernel_launch(void* const* d_in, const int* in_sizes, int n_in,
                              void* d_out, int out_size)
{
    const float* x  = (const float*)d_in[0];
    const float* Wq = (const float*)d_in[1];
    const float* bq = (const float*)d_in[2];
    const float* Wk = (const float*)d_in[3];
    const float* bk = (const float*)d_in[4];
    const float* Wv = (const float*)d_in[5];
    const float* bv = (const float*)d_in[6];
    const float* Wo = (const float*)d_in[7];
    const float* bo = (const float*)d_in[8];
    const float* m  = (const float*)d_in[9];
    float* out = (float*)d_out;

    float *q, *k, *v, *S, *Sp;
    __half *xh, *ah, *wth;
    cudaGetSymbolAddress((void**)&q, g_q);
    cudaGetSymbolAddress((void**)&k, g_k);
    cudaGetSymbolAddress((void**)&v, g_v);
    cudaGetSymbolAddress((void**)&S, g_S);
    cudaGetSymbolAddress((void**)&Sp, g_Sp);
    cudaGetSymbolAddress((void**)&xh, g_xh);
    cudaGetSymbolAddress((void**)&ah, g_ah);
    cudaGetSymbolAddress((void**)&wth, g_wth);

    cudaFuncSetAttribute(gemm1_kernel,
                         cudaFuncAttributeMaxDynamicSharedMemorySize, GSMEM);

    // converts
    tofp16_kernel<<<MROWS * FEATS / 4 / 256, 256>>>(x, xh, MROWS * FEATS / 4);
    wsplit_kernel<<<dim3(32, 32, 4), 256>>>(Wq, Wk, Wv, Wo, wth);

    // fused QKV projections + bias + Q/K L2 norm
    gemm1_kernel<<<dim3(1024 / TBN, MROWS / TBM, 3), 256, GSMEM>>>(
        xh, wth, bq, bk, bv, q, k, v, 2);

    ktv_partial_kernel<<<512, 256>>>(k, v, Sp);
    ktv_reduce_kernel<<<64, 256>>>(Sp, m, S);

    qs_kernel<<<dim3(NTOK / 64, 64), 256>>>(q, S, ah);

    // output projection
    gemm1_kernel<<<dim3(1024 / TBN, MROWS / TBM, 1), 256, GSMEM>>>(
        ah, wth + 3 * (size_t)WSZ,
        bo, bo, bo, out, out, out, 0);
}